// round 1
// baseline (speedup 1.0000x reference)
#include <cuda_runtime.h>

#define NNODES 50000
#define NEDGES 600000
#define TOTE (NEDGES + NNODES)
#define BN_EPS 1e-5f
#define NEG_SLOPE 0.2f

// ---------------- scratch (static device globals; no allocation) ----------------
__device__ float4 g_bufA[NNODES * 32];   // 25.6 MB
__device__ float4 g_bufB[NNODES * 32];   // 25.6 MB
__device__ float4 g_hlin[NNODES * 32];   // 25.6 MB  (h = x@W per layer)
__device__ float4 g_gout[NNODES * 32];   // 25.6 MB  (GAT output per layer)
__device__ float4 g_asrc[NNODES];        // alpha_src [N][4]
__device__ float4 g_adst[NNODES];        // alpha_dst [N][4]
__device__ int    g_deg[NNODES];
__device__ int    g_rowstart[NNODES + 1];
__device__ int    g_cursor[NNODES];
__device__ int    g_csr[TOTE];
__device__ float  g_bnsum[128];
__device__ float  g_bnsq[128];

// ---------------- f32x2 packed-FMA helpers (sm_100+ FFMA2 path) ----------------
__device__ __forceinline__ void pack2(unsigned long long& d, float lo, float hi) {
    asm("mov.b64 %0, {%1, %2};" : "=l"(d) : "f"(lo), "f"(hi));
}
__device__ __forceinline__ void unpack2(float& lo, float& hi, unsigned long long s) {
    asm("mov.b64 {%0, %1}, %2;" : "=f"(lo), "=f"(hi) : "l"(s));
}
__device__ __forceinline__ void fma2(unsigned long long& acc, unsigned long long a,
                                     unsigned long long b) {
    asm("fma.rn.f32x2 %0, %1, %2, %0;" : "+l"(acc) : "l"(a), "l"(b));
}

__device__ __forceinline__ float lrelu(float x) { return x > 0.f ? x : NEG_SLOPE * x; }
__device__ __forceinline__ float selc(const float4& v, int kk) {
    return kk == 0 ? v.x : (kk == 1 ? v.y : (kk == 2 ? v.z : v.w));
}

// ---------------- CSR build ----------------
__global__ void init_deg_kernel() {
    int i = blockIdx.x * blockDim.x + threadIdx.x;
    if (i < NNODES) g_deg[i] = 1;  // self loop
}

__global__ void count_kernel(const int* __restrict__ ei, int E) {
    int e = blockIdx.x * blockDim.x + threadIdx.x;
    if (e < E) atomicAdd(&g_deg[ei[E + e]], 1);
}

// single-block exclusive scan over g_deg -> g_rowstart (warp-scan based)
__global__ void scan_kernel() {
    __shared__ int wsum[32];
    __shared__ int carry_s;
    int tid = threadIdx.x;           // 1024
    int lane = tid & 31, wid = tid >> 5;
    if (tid == 0) carry_s = 0;
    __syncthreads();
    for (int base = 0; base < NNODES; base += 1024) {
        int i = base + tid;
        int v = (i < NNODES) ? g_deg[i] : 0;
        int x = v;
#pragma unroll
        for (int o = 1; o < 32; o <<= 1) {
            int t = __shfl_up_sync(0xffffffffu, x, o);
            if (lane >= o) x += t;
        }
        if (lane == 31) wsum[wid] = x;
        __syncthreads();
        if (wid == 0) {
            int y = wsum[lane];
#pragma unroll
            for (int o = 1; o < 32; o <<= 1) {
                int t = __shfl_up_sync(0xffffffffu, y, o);
                if (lane >= o) y += t;
            }
            wsum[lane] = y;
        }
        __syncthreads();
        int offset = (wid > 0) ? wsum[wid - 1] : 0;
        int incl = x + offset;
        int c = carry_s;
        if (i < NNODES) g_rowstart[i] = c + incl - v;
        int total = wsum[31];
        __syncthreads();
        if (tid == 0) carry_s = c + total;
        __syncthreads();
    }
    if (threadIdx.x == 0) g_rowstart[NNODES] = carry_s;
}

__global__ void selfloop_kernel() {
    int i = blockIdx.x * blockDim.x + threadIdx.x;
    if (i < NNODES) {
        int rs = g_rowstart[i];
        g_csr[rs] = i;          // self loop first in segment
        g_cursor[i] = rs + 1;
    }
}

__global__ void scatter_kernel(const int* __restrict__ ei, int E) {
    int e = blockIdx.x * blockDim.x + threadIdx.x;
    if (e < E) {
        int d = ei[E + e];
        int p = atomicAdd(&g_cursor[d], 1);
        g_csr[p] = ei[e];
    }
}

// ---------------- GEMM: h = X @ W  (50000x128 @ 128x128), packed f32x2 ----------------
__global__ __launch_bounds__(256) void gemm_kernel(int insel, const float* __restrict__ xext,
                                                   const float* __restrict__ W) {
    const float4* X = (insel == 0) ? (const float4*)xext : (insel == 1 ? g_bufA : g_bufB);
    __shared__ float4 xs[64 * 32];  // 64 rows x 128 cols fp32 = 32 KB
    int tid = threadIdx.x;
    int row0 = blockIdx.x * 64;
#pragma unroll
    for (int i = 0; i < 8; i++) {
        int id = tid + 256 * i;
        int r = id >> 5, kq = id & 31;
        float4 v = make_float4(0.f, 0.f, 0.f, 0.f);
        int gr = row0 + r;
        if (gr < NNODES) v = X[gr * 32 + kq];
        xs[r * 32 + kq] = v;
    }
    __syncthreads();

    int cx = tid & 31;   // cols 4cx..4cx+3
    int ry = tid >> 5;   // rows 8ry..8ry+7 of tile
    unsigned long long acc[4][4];
#pragma unroll
    for (int p = 0; p < 4; p++)
#pragma unroll
        for (int c = 0; c < 4; c++) acc[p][c] = 0ULL;

    const float4* W4 = (const float4*)W;
    const float4* xrow = &xs[(ry * 8) * 32];

#pragma unroll 2
    for (int k4 = 0; k4 < 32; k4++) {
        float4 xv[8];
#pragma unroll
        for (int r = 0; r < 8; r++) xv[r] = xrow[r * 32 + k4];
#pragma unroll
        for (int kk = 0; kk < 4; kk++) {
            int k = k4 * 4 + kk;
            float4 w = __ldg(&W4[k * 32 + cx]);
            unsigned long long wd[4];
            pack2(wd[0], w.x, w.x);
            pack2(wd[1], w.y, w.y);
            pack2(wd[2], w.z, w.z);
            pack2(wd[3], w.w, w.w);
#pragma unroll
            for (int p = 0; p < 4; p++) {
                unsigned long long xp;
                pack2(xp, selc(xv[2 * p], kk), selc(xv[2 * p + 1], kk));
                fma2(acc[p][0], xp, wd[0]);
                fma2(acc[p][1], xp, wd[1]);
                fma2(acc[p][2], xp, wd[2]);
                fma2(acc[p][3], xp, wd[3]);
            }
        }
    }

#pragma unroll
    for (int p = 0; p < 4; p++) {
        float lo0, hi0, lo1, hi1, lo2, hi2, lo3, hi3;
        unpack2(lo0, hi0, acc[p][0]);
        unpack2(lo1, hi1, acc[p][1]);
        unpack2(lo2, hi2, acc[p][2]);
        unpack2(lo3, hi3, acc[p][3]);
        int r0 = row0 + ry * 8 + 2 * p;
        if (r0 < NNODES) g_hlin[r0 * 32 + cx] = make_float4(lo0, lo1, lo2, lo3);
        if (r0 + 1 < NNODES) g_hlin[(r0 + 1) * 32 + cx] = make_float4(hi0, hi1, hi2, hi3);
    }
}

// ---------------- alpha_src/alpha_dst per node (+ zero BN accumulators) ----------------
__global__ __launch_bounds__(256) void alpha_kernel(const float4* __restrict__ as4,
                                                    const float4* __restrict__ ad4) {
    if (blockIdx.x == 0) {
        int t = threadIdx.x;
        if (t < 128) g_bnsum[t] = 0.f;
        else g_bnsq[t - 128] = 0.f;
    }
    int gt = blockIdx.x * blockDim.x + threadIdx.x;
    int warp = gt >> 5;
    int lane = gt & 31;
    if (warp >= NNODES) return;
    float4 v = g_hlin[warp * 32 + lane];
    int hh = lane >> 3, q = lane & 7;
    float4 a = as4[hh * 8 + q];
    float4 b = ad4[hh * 8 + q];
    float ds = v.x * a.x + v.y * a.y + v.z * a.z + v.w * a.w;
    float dd = v.x * b.x + v.y * b.y + v.z * b.z + v.w * b.w;
#pragma unroll
    for (int o = 4; o > 0; o >>= 1) {
        ds += __shfl_xor_sync(0xffffffffu, ds, o);
        dd += __shfl_xor_sync(0xffffffffu, dd, o);
    }
    if (q == 0) {
        ((float*)g_asrc)[warp * 4 + hh] = ds;
        ((float*)g_adst)[warp * 4 + hh] = dd;
    }
}

// ---------------- warp-per-dst segment softmax + weighted aggregation ----------------
__global__ __launch_bounds__(256) void aggregate_kernel(const float* __restrict__ bias) {
    int gt = blockIdx.x * blockDim.x + threadIdx.x;
    int warp = gt >> 5;
    int lane = gt & 31;
    if (warp >= NNODES) return;
    int rs = g_rowstart[warp];
    int re = g_rowstart[warp + 1];
    const float* adp = (const float*)&g_adst[warp];
    float ad0 = adp[0], ad1 = adp[1], ad2 = adp[2], ad3 = adp[3];

    // phase 1: segment max per head
    float m0 = -3.0e38f, m1 = -3.0e38f, m2 = -3.0e38f, m3 = -3.0e38f;
    for (int j = rs + lane; j < re; j += 32) {
        int s = g_csr[j];
        float4 av = g_asrc[s];
        m0 = fmaxf(m0, lrelu(av.x + ad0));
        m1 = fmaxf(m1, lrelu(av.y + ad1));
        m2 = fmaxf(m2, lrelu(av.z + ad2));
        m3 = fmaxf(m3, lrelu(av.w + ad3));
    }
#pragma unroll
    for (int o = 16; o > 0; o >>= 1) {
        m0 = fmaxf(m0, __shfl_xor_sync(0xffffffffu, m0, o));
        m1 = fmaxf(m1, __shfl_xor_sync(0xffffffffu, m1, o));
        m2 = fmaxf(m2, __shfl_xor_sync(0xffffffffu, m2, o));
        m3 = fmaxf(m3, __shfl_xor_sync(0xffffffffu, m3, o));
    }

    // phase 2: segment sum of exp
    float t0 = 0.f, t1 = 0.f, t2 = 0.f, t3 = 0.f;
    for (int j = rs + lane; j < re; j += 32) {
        int s = g_csr[j];
        float4 av = g_asrc[s];
        t0 += __expf(lrelu(av.x + ad0) - m0);
        t1 += __expf(lrelu(av.y + ad1) - m1);
        t2 += __expf(lrelu(av.z + ad2) - m2);
        t3 += __expf(lrelu(av.w + ad3) - m3);
    }
#pragma unroll
    for (int o = 16; o > 0; o >>= 1) {
        t0 += __shfl_xor_sync(0xffffffffu, t0, o);
        t1 += __shfl_xor_sync(0xffffffffu, t1, o);
        t2 += __shfl_xor_sync(0xffffffffu, t2, o);
        t3 += __shfl_xor_sync(0xffffffffu, t3, o);
    }

    // phase 3: weighted sum of h[src]; lane owns channels 4*lane..4*lane+3, head = lane/8
    int hh = lane >> 3;
    float mh = hh == 0 ? m0 : (hh == 1 ? m1 : (hh == 2 ? m2 : m3));
    float sh = hh == 0 ? t0 : (hh == 1 ? t1 : (hh == 2 ? t2 : t3));
    float adh = hh == 0 ? ad0 : (hh == 1 ? ad1 : (hh == 2 ? ad2 : ad3));
    float invs = 1.0f / sh;
    float4 acc = make_float4(0.f, 0.f, 0.f, 0.f);
    const float* asf = (const float*)g_asrc;
    for (int j = rs; j < re; j++) {
        int s = g_csr[j];
        float a = asf[s * 4 + hh];
        float coef = __expf(lrelu(a + adh) - mh) * invs;
        float4 hv = g_hlin[s * 32 + lane];
        acc.x = fmaf(coef, hv.x, acc.x);
        acc.y = fmaf(coef, hv.y, acc.y);
        acc.z = fmaf(coef, hv.z, acc.z);
        acc.w = fmaf(coef, hv.w, acc.w);
    }
    float4 b = ((const float4*)bias)[lane];
    g_gout[warp * 32 + lane] = make_float4(acc.x + b.x, acc.y + b.y, acc.z + b.z, acc.w + b.w);
}

// ---------------- BN channel reduce ----------------
__global__ __launch_bounds__(128) void bn_reduce_kernel() {
    int c = threadIdx.x;  // 128
    float s = 0.f, q = 0.f;
    const float* G = (const float*)g_gout;
    for (int r = blockIdx.x; r < NNODES; r += gridDim.x) {
        float v = G[r * 128 + c];
        s += v;
        q = fmaf(v, v, q);
    }
    atomicAdd(&g_bnsum[c], s);
    atomicAdd(&g_bnsq[c], q);
}

// ---------------- BN apply + ReLU (+ residual), write next buffer ----------------
__global__ __launch_bounds__(256) void bn_apply_kernel(int outsel, float* __restrict__ outext,
                                                       int ressel,
                                                       const float* __restrict__ gamma,
                                                       const float* __restrict__ beta) {
    float4* OUT = (outsel == 0) ? (float4*)outext : (outsel == 1 ? g_bufA : g_bufB);
    const float4* RES = (ressel == 0) ? nullptr : (ressel == 1 ? g_bufA : g_bufB);
    int i = blockIdx.x * blockDim.x + threadIdx.x;  // over NNODES*32 float4s (exact)
    if (i >= NNODES * 32) return;
    int c4 = i & 31;
    const float invN = 1.0f / (float)NNODES;
    float4 s = ((const float4*)g_bnsum)[c4];
    float4 q = ((const float4*)g_bnsq)[c4];
    float4 g = ((const float4*)gamma)[c4];
    float4 bt = ((const float4*)beta)[c4];
    float mux = s.x * invN, muy = s.y * invN, muz = s.z * invN, muw = s.w * invN;
    float scx = g.x * rsqrtf(fmaxf(q.x * invN - mux * mux, 0.f) + BN_EPS);
    float scy = g.y * rsqrtf(fmaxf(q.y * invN - muy * muy, 0.f) + BN_EPS);
    float scz = g.z * rsqrtf(fmaxf(q.z * invN - muz * muz, 0.f) + BN_EPS);
    float scw = g.w * rsqrtf(fmaxf(q.w * invN - muw * muw, 0.f) + BN_EPS);
    float shx = bt.x - mux * scx, shy = bt.y - muy * scy;
    float shz = bt.z - muz * scz, shw = bt.w - muw * scw;
    float4 v = g_gout[i];
    float rx = fmaf(v.x, scx, shx), ry_ = fmaf(v.y, scy, shy);
    float rz = fmaf(v.z, scz, shz), rw = fmaf(v.w, scw, shw);
    if (RES) {
        float4 id = RES[i];
        rx += id.x; ry_ += id.y; rz += id.z; rw += id.w;
    }
    OUT[i] = make_float4(fmaxf(rx, 0.f), fmaxf(ry_, 0.f), fmaxf(rz, 0.f), fmaxf(rw, 0.f));
}

// ---------------- launcher ----------------
extern "C" void kernel_launch(void* const* d_in, const int* in_sizes, int n_in,
                              void* d_out, int out_size) {
    const float* x = (const float*)d_in[0];
    const int* ei = (const int*)d_in[1];
    const float* Ws = (const float*)d_in[2];
    const float* att_src = (const float*)d_in[3];
    const float* att_dst = (const float*)d_in[4];
    const float* biases = (const float*)d_in[5];
    const float* gammas = (const float*)d_in[6];
    const float* betas = (const float*)d_in[7];
    int E = in_sizes[1] / 2;

    // CSR build (dst-sorted adjacency with self loops first)
    init_deg_kernel<<<(NNODES + 255) / 256, 256>>>();
    count_kernel<<<(E + 255) / 256, 256>>>(ei, E);
    scan_kernel<<<1, 1024>>>();
    selfloop_kernel<<<(NNODES + 255) / 256, 256>>>();
    scatter_kernel<<<(E + 255) / 256, 256>>>(ei, E);

    // layer configs: {gemm input sel, bn output sel, residual sel}
    // sel: 0=external(x / d_out), 1=g_bufA, 2=g_bufB
    const int insel[6]  = {0, 1, 2, 1, 1, 2};
    const int outsel[6] = {1, 2, 1, 1, 2, 0};
    const int ressel[6] = {0, 0, 0, 2, 0, 1};

    const int gemm_blocks = (NNODES + 63) / 64;
    const int warp_blocks = (NNODES * 32) / 256;  // 6250 exact

    for (int l = 0; l < 6; l++) {
        gemm_kernel<<<gemm_blocks, 256>>>(insel[l], x, Ws + l * 128 * 128);
        alpha_kernel<<<warp_blocks, 256>>>((const float4*)(att_src + l * 128),
                                           (const float4*)(att_dst + l * 128));
        aggregate_kernel<<<warp_blocks, 256>>>(biases + l * 128);
        bn_reduce_kernel<<<512, 128>>>();
        bn_apply_kernel<<<warp_blocks, 256>>>(outsel[l], (float*)d_out, ressel[l],
                                              gammas + l * 128, betas + l * 128);
    }
}

// round 11
// speedup vs baseline: 1.2924x; 1.2924x over previous
#include <cuda_runtime.h>

#define NNODES 50000
#define NEDGES 600000
#define TOTE (NEDGES + NNODES)
#define BN_EPS 1e-5f
#define NEG_SLOPE 0.2f

// ---------------- scratch (static device globals; no allocation) ----------------
__device__ float4 g_bufA[NNODES * 32];   // 25.6 MB (materialized h1 / residuals)
__device__ float4 g_bufB[NNODES * 32];   // 25.6 MB (materialized h3 / residuals)
__device__ float4 g_hlin[NNODES * 32];   // 25.6 MB  (h = x@W per layer)
__device__ float4 g_gout[NNODES * 32];   // 25.6 MB  (raw GAT output per layer)
__device__ float4 g_asrc[NNODES];        // alpha_src [N][4]
__device__ float4 g_adst[NNODES];        // alpha_dst [N][4]
__device__ int    g_deg[NNODES];
__device__ int    g_rowstart[NNODES + 1];
__device__ int    g_cursor[NNODES];
__device__ int    g_csr[TOTE];
__device__ float  g_bnsum[6][128];
__device__ float  g_bnsq[6][128];

// ---------------- f32x2 packed-FMA helpers (sm_100+ FFMA2 path) ----------------
__device__ __forceinline__ void pack2(unsigned long long& d, float lo, float hi) {
    asm("mov.b64 %0, {%1, %2};" : "=l"(d) : "f"(lo), "f"(hi));
}
__device__ __forceinline__ void unpack2(float& lo, float& hi, unsigned long long s) {
    asm("mov.b64 {%0, %1}, %2;" : "=f"(lo), "=f"(hi) : "l"(s));
}
__device__ __forceinline__ void fma2(unsigned long long& acc, unsigned long long a,
                                     unsigned long long b) {
    asm("fma.rn.f32x2 %0, %1, %2, %0;" : "+l"(acc) : "l"(a), "l"(b));
}

__device__ __forceinline__ float lrelu(float x) { return x > 0.f ? x : NEG_SLOPE * x; }

// ---------------- init: zero BN accumulators ----------------
__global__ void zero_bn_kernel() {
    int i = blockIdx.x * blockDim.x + threadIdx.x;
    if (i < 6 * 128) {
        ((float*)g_bnsum)[i] = 0.f;
        ((float*)g_bnsq)[i] = 0.f;
    }
}

// ---------------- CSR build ----------------
__global__ void init_deg_kernel() {
    int i = blockIdx.x * blockDim.x + threadIdx.x;
    if (i < NNODES) g_deg[i] = 1;  // self loop
}

__global__ void count_kernel(const int* __restrict__ ei, int E) {
    int e = blockIdx.x * blockDim.x + threadIdx.x;
    if (e < E) atomicAdd(&g_deg[ei[E + e]], 1);
}

// single-block exclusive scan over g_deg -> g_rowstart (warp-scan based)
__global__ void scan_kernel() {
    __shared__ int wsum[32];
    __shared__ int carry_s;
    int tid = threadIdx.x;           // 1024
    int lane = tid & 31, wid = tid >> 5;
    if (tid == 0) carry_s = 0;
    __syncthreads();
    for (int base = 0; base < NNODES; base += 1024) {
        int i = base + tid;
        int v = (i < NNODES) ? g_deg[i] : 0;
        int x = v;
#pragma unroll
        for (int o = 1; o < 32; o <<= 1) {
            int t = __shfl_up_sync(0xffffffffu, x, o);
            if (lane >= o) x += t;
        }
        if (lane == 31) wsum[wid] = x;
        __syncthreads();
        if (wid == 0) {
            int y = wsum[lane];
#pragma unroll
            for (int o = 1; o < 32; o <<= 1) {
                int t = __shfl_up_sync(0xffffffffu, y, o);
                if (lane >= o) y += t;
            }
            wsum[lane] = y;
        }
        __syncthreads();
        int offset = (wid > 0) ? wsum[wid - 1] : 0;
        int incl = x + offset;
        int c = carry_s;
        if (i < NNODES) g_rowstart[i] = c + incl - v;
        int total = wsum[31];
        __syncthreads();
        if (tid == 0) carry_s = c + total;
        __syncthreads();
    }
    if (threadIdx.x == 0) g_rowstart[NNODES] = carry_s;
}

__global__ void selfloop_kernel() {
    int i = blockIdx.x * blockDim.x + threadIdx.x;
    if (i < NNODES) {
        int rs = g_rowstart[i];
        g_csr[rs] = i;          // self loop first in segment
        g_cursor[i] = rs + 1;
    }
}

__global__ void scatter_kernel(const int* __restrict__ ei, int E) {
    int e = blockIdx.x * blockDim.x + threadIdx.x;
    if (e < E) {
        int d = ei[E + e];
        int p = atomicAdd(&g_cursor[d], 1);
        g_csr[p] = ei[e];
    }
}

// ---------------- GEMM: h = X @ W (mov-free f32x2 inner loop) ------------------
// Tile: 32 rows/block, 256 threads. Thread (cx = lane: cols 4cx..4cx+3 as 2 col
// pairs; ry = warp: rows ry*4..ry*4+3). X staged in smem PRE-DUPLICATED as
// (x,x) doubles [row][k] -> inner-loop LDS.128 yields 2 k-steps, warp-uniform
// broadcast. W columns are paired by reinterpreting fp32 LDG.128 as 2x 64-bit
// operands -> zero pack movs in the k loop.
// mode: 0 = load xext; 1 = g_bufA; 2 = g_bufB; 3 = g_gout with fused BN+ReLU.
__global__ __launch_bounds__(256) void gemm_kernel(int mode, const float* __restrict__ xext,
                                                   const float* __restrict__ W,
                                                   const float* __restrict__ atts,
                                                   const float* __restrict__ attd,
                                                   const float* __restrict__ gamma,
                                                   const float* __restrict__ beta,
                                                   int sidx) {
    const float4* X = (mode == 0) ? (const float4*)xext
                                  : (mode == 1 ? g_bufA : (mode == 2 ? g_bufB : g_gout));
    __shared__ unsigned long long xs[32 * 128];  // 32 rows x 128 k, dup doubles = 32KB
    __shared__ float sc[128], shv[128];
    int tid = threadIdx.x;
    if (mode == 3 && tid < 128) {
        const float invN = 1.0f / (float)NNODES;
        float s = g_bnsum[sidx][tid];
        float q = g_bnsq[sidx][tid];
        float mu = s * invN;
        float scl = gamma[tid] * rsqrtf(fmaxf(q * invN - mu * mu, 0.f) + BN_EPS);
        sc[tid] = scl;
        shv[tid] = beta[tid] - mu * scl;
    }
    __syncthreads();

    int row0 = blockIdx.x * 32;
    int kq = tid & 31;   // k-quad 0..31
    int rr = tid >> 5;   // row 0..7 (+8 per iter)
#pragma unroll
    for (int i = 0; i < 4; i++) {
        int r = rr + 8 * i;
        int gr = row0 + r;
        float4 v = make_float4(0.f, 0.f, 0.f, 0.f);
        if (gr < NNODES) v = X[gr * 32 + kq];
        if (mode == 3) {
            int c = 4 * kq;
            v.x = fmaxf(fmaf(v.x, sc[c], shv[c]), 0.f);
            v.y = fmaxf(fmaf(v.y, sc[c + 1], shv[c + 1]), 0.f);
            v.z = fmaxf(fmaf(v.z, sc[c + 2], shv[c + 2]), 0.f);
            v.w = fmaxf(fmaf(v.w, sc[c + 3], shv[c + 3]), 0.f);
        }
        unsigned long long d0, d1, d2, d3;
        pack2(d0, v.x, v.x);
        pack2(d1, v.y, v.y);
        pack2(d2, v.z, v.z);
        pack2(d3, v.w, v.w);
        ulonglong2* p = (ulonglong2*)&xs[r * 128 + 4 * kq];
        p[0] = make_ulonglong2(d0, d1);
        p[1] = make_ulonglong2(d2, d3);
    }
    __syncthreads();

    int cx = tid & 31;   // cols 4cx..4cx+3
    int ry = tid >> 5;   // rows ry*4..ry*4+3
    unsigned long long acc[4][2];
#pragma unroll
    for (int r = 0; r < 4; r++) { acc[r][0] = 0ULL; acc[r][1] = 0ULL; }

    const char* Wb = (const char*)W;
    const unsigned long long* xrow = &xs[(ry * 4) * 128];

#pragma unroll 4
    for (int k = 0; k < 128; k += 2) {
        // (w_{k,4cx}, w_{k,4cx+1}) and (w_{k,4cx+2}, w_{k,4cx+3}) as 64-bit pairs
        ulonglong2 w0 = *(const ulonglong2*)(Wb + (unsigned)k * 512u + (unsigned)cx * 16u);
        ulonglong2 w1 = *(const ulonglong2*)(Wb + (unsigned)(k + 1) * 512u + (unsigned)cx * 16u);
        ulonglong2 xp0 = *(const ulonglong2*)&xrow[0 * 128 + k];
        ulonglong2 xp1 = *(const ulonglong2*)&xrow[1 * 128 + k];
        ulonglong2 xp2 = *(const ulonglong2*)&xrow[2 * 128 + k];
        ulonglong2 xp3 = *(const ulonglong2*)&xrow[3 * 128 + k];
        fma2(acc[0][0], xp0.x, w0.x); fma2(acc[0][1], xp0.x, w0.y);
        fma2(acc[1][0], xp1.x, w0.x); fma2(acc[1][1], xp1.x, w0.y);
        fma2(acc[2][0], xp2.x, w0.x); fma2(acc[2][1], xp2.x, w0.y);
        fma2(acc[3][0], xp3.x, w0.x); fma2(acc[3][1], xp3.x, w0.y);
        fma2(acc[0][0], xp0.y, w1.x); fma2(acc[0][1], xp0.y, w1.y);
        fma2(acc[1][0], xp1.y, w1.x); fma2(acc[1][1], xp1.y, w1.y);
        fma2(acc[2][0], xp2.y, w1.x); fma2(acc[2][1], xp2.y, w1.y);
        fma2(acc[3][0], xp3.y, w1.x); fma2(acc[3][1], xp3.y, w1.y);
    }

    // epilogue: store h + fused alpha_src/alpha_dst (8-lane reduce per head group)
    float4 as4 = ((const float4*)atts)[cx];
    float4 ad4 = ((const float4*)attd)[cx];
    float* asrcf = (float*)g_asrc;
    float* adstf = (float*)g_adst;
#pragma unroll
    for (int r = 0; r < 4; r++) {
        float c0, c1, c2, c3;
        unpack2(c0, c1, acc[r][0]);   // cols 4cx, 4cx+1
        unpack2(c2, c3, acc[r][1]);   // cols 4cx+2, 4cx+3
        int gr = row0 + ry * 4 + r;
        float ps = c0 * as4.x + c1 * as4.y + c2 * as4.z + c3 * as4.w;
        float pd = c0 * ad4.x + c1 * ad4.y + c2 * ad4.z + c3 * ad4.w;
#pragma unroll
        for (int o = 4; o > 0; o >>= 1) {
            ps += __shfl_xor_sync(0xffffffffu, ps, o);
            pd += __shfl_xor_sync(0xffffffffu, pd, o);
        }
        if (gr < NNODES) {
            g_hlin[gr * 32 + cx] = make_float4(c0, c1, c2, c3);
            if ((cx & 7) == 0) {
                int hh = cx >> 3;
                asrcf[gr * 4 + hh] = ps;
                adstf[gr * 4 + hh] = pd;
            }
        }
    }
}

// ---------------- warp-per-dst ONE-PASS softmax aggregation
// out = (sum_j e_j * h[s_j]) / (sum_j e_j) + bias  (shift-free softmax)
// + fused BN channel reduction (block partials -> atomicAdd)
__global__ __launch_bounds__(256) void aggregate_kernel(const float* __restrict__ bias,
                                                        int sidx) {
    __shared__ float bsum[8][128];
    __shared__ float bsq[8][128];
    int tid = threadIdx.x;
    int w = tid >> 5;
    int lane = tid & 31;
    int node = blockIdx.x * 8 + w;  // grid = 6250 blocks, exact cover of 50000

    int rs = g_rowstart[node];
    int re = g_rowstart[node + 1];
    int hh = lane >> 3;
    float adh = ((const float*)g_adst)[node * 4 + hh];

    float esum = 0.f;
    float4 acc = make_float4(0.f, 0.f, 0.f, 0.f);
    const float* asf = (const float*)g_asrc;
#pragma unroll 4
    for (int j = rs; j < re; j++) {
        int s = g_csr[j];
        float a = asf[s * 4 + hh];
        float e = __expf(lrelu(a + adh));
        esum += e;
        float4 hv = g_hlin[s * 32 + lane];
        acc.x = fmaf(e, hv.x, acc.x);
        acc.y = fmaf(e, hv.y, acc.y);
        acc.z = fmaf(e, hv.z, acc.z);
        acc.w = fmaf(e, hv.w, acc.w);
    }
    float invs = 1.0f / esum;
    float4 b = ((const float4*)bias)[lane];
    float ox = fmaf(acc.x, invs, b.x), oy = fmaf(acc.y, invs, b.y);
    float oz = fmaf(acc.z, invs, b.z), ow = fmaf(acc.w, invs, b.w);
    g_gout[node * 32 + lane] = make_float4(ox, oy, oz, ow);

    // fused BN partial reduction
    int c = 4 * lane;
    bsum[w][c] = ox;         bsum[w][c + 1] = oy;
    bsum[w][c + 2] = oz;     bsum[w][c + 3] = ow;
    bsq[w][c] = ox * ox;     bsq[w][c + 1] = oy * oy;
    bsq[w][c + 2] = oz * oz; bsq[w][c + 3] = ow * ow;
    __syncthreads();
    if (tid < 128) {
        float s = 0.f;
#pragma unroll
        for (int r = 0; r < 8; r++) s += bsum[r][tid];
        atomicAdd(&g_bnsum[sidx][tid], s);
    } else {
        int t = tid - 128;
        float s = 0.f;
#pragma unroll
        for (int r = 0; r < 8; r++) s += bsq[r][t];
        atomicAdd(&g_bnsq[sidx][t], s);
    }
}

// ---------------- BN apply + ReLU (+ residual); only for materialized layers -------
__global__ __launch_bounds__(256) void bn_apply_kernel(int outsel, float* __restrict__ outext,
                                                       int ressel,
                                                       const float* __restrict__ gamma,
                                                       const float* __restrict__ beta,
                                                       int sidx) {
    float4* OUT = (outsel == 0) ? (float4*)outext : (outsel == 1 ? g_bufA : g_bufB);
    const float4* RES = (ressel == 0) ? nullptr : (ressel == 1 ? g_bufA : g_bufB);
    int i = blockIdx.x * blockDim.x + threadIdx.x;  // over NNODES*32 float4s (exact)
    int c4 = i & 31;
    const float invN = 1.0f / (float)NNODES;
    float4 s = ((const float4*)g_bnsum[sidx])[c4];
    float4 q = ((const float4*)g_bnsq[sidx])[c4];
    float4 g = ((const float4*)gamma)[c4];
    float4 bt = ((const float4*)beta)[c4];
    float mux = s.x * invN, muy = s.y * invN, muz = s.z * invN, muw = s.w * invN;
    float scx = g.x * rsqrtf(fmaxf(q.x * invN - mux * mux, 0.f) + BN_EPS);
    float scy = g.y * rsqrtf(fmaxf(q.y * invN - muy * muy, 0.f) + BN_EPS);
    float scz = g.z * rsqrtf(fmaxf(q.z * invN - muz * muz, 0.f) + BN_EPS);
    float scw = g.w * rsqrtf(fmaxf(q.w * invN - muw * muw, 0.f) + BN_EPS);
    float shx = bt.x - mux * scx, shy = bt.y - muy * scy;
    float shz = bt.z - muz * scz, shw = bt.w - muw * scw;
    float4 v = g_gout[i];
    float rx = fmaf(v.x, scx, shx), ry_ = fmaf(v.y, scy, shy);
    float rz = fmaf(v.z, scz, shz), rw = fmaf(v.w, scw, shw);
    if (RES) {
        float4 id = RES[i];
        rx += id.x; ry_ += id.y; rz += id.z; rw += id.w;
    }
    OUT[i] = make_float4(fmaxf(rx, 0.f), fmaxf(ry_, 0.f), fmaxf(rz, 0.f), fmaxf(rw, 0.f));
}

// ---------------- launcher ----------------
extern "C" void kernel_launch(void* const* d_in, const int* in_sizes, int n_in,
                              void* d_out, int out_size) {
    const float* x = (const float*)d_in[0];
    const int* ei = (const int*)d_in[1];
    const float* Ws = (const float*)d_in[2];
    const float* att_src = (const float*)d_in[3];
    const float* att_dst = (const float*)d_in[4];
    const float* biases = (const float*)d_in[5];
    const float* gammas = (const float*)d_in[6];
    const float* betas = (const float*)d_in[7];
    int E = in_sizes[1] / 2;

    zero_bn_kernel<<<3, 256>>>();
    // CSR build (dst-sorted adjacency with self loops first)
    init_deg_kernel<<<(NNODES + 255) / 256, 256>>>();
    count_kernel<<<(E + 255) / 256, 256>>>(ei, E);
    scan_kernel<<<1, 1024>>>();
    selfloop_kernel<<<(NNODES + 255) / 256, 256>>>();
    scatter_kernel<<<(E + 255) / 256, 256>>>(ei, E);

    // gemm mode per layer: 0=x, 1=bufA, 2=bufB, 3=fused-BN from g_gout (stats l-1)
    const int mode[6] = {0, 3, 1, 3, 2, 3};

    const int gemm_blocks = (NNODES + 31) / 32;   // 1563
    const int warp_blocks = (NNODES * 32) / 256;  // 6250 exact

    for (int l = 0; l < 6; l++) {
        const float* gm1 = (l > 0) ? gammas + (l - 1) * 128 : nullptr;
        const float* bt1 = (l > 0) ? betas + (l - 1) * 128 : nullptr;
        gemm_kernel<<<gemm_blocks, 256>>>(mode[l], x, Ws + l * 128 * 128,
                                          att_src + l * 128, att_dst + l * 128,
                                          gm1, bt1, l - 1);
        aggregate_kernel<<<warp_blocks, 256>>>(biases + l * 128, l);
        if (l == 1)
            bn_apply_kernel<<<warp_blocks, 256>>>(1, (float*)d_out, 0,
                                                  gammas + 128, betas + 128, 1);
        else if (l == 3)
            bn_apply_kernel<<<warp_blocks, 256>>>(2, (float*)d_out, 1,
                                                  gammas + 3 * 128, betas + 3 * 128, 3);
        else if (l == 5)
            bn_apply_kernel<<<warp_blocks, 256>>>(0, (float*)d_out, 2,
                                                  gammas + 5 * 128, betas + 5 * 128, 5);
    }
}